// round 5
// baseline (speedup 1.0000x reference)
#include <cuda_runtime.h>
#include <math.h>
#include <stdint.h>

#define FULLMASK 0xffffffffu

__device__ __align__(16) float g_y1[64 * 320 * 768];
__device__ __align__(16) float g_y2[64 * 224 * 512];
__device__ __align__(16) float g_y3[64 * 144 * 256];
__device__ __align__(16) float g_y4[64 * 88 * 4];

__device__ __forceinline__ unsigned long long fma2(unsigned long long a,
                                                   unsigned long long b,
                                                   unsigned long long c) {
    unsigned long long d;
    asm("fma.rn.f32x2 %0,%1,%2,%3;" : "=l"(d) : "l"(a), "l"(b), "l"(c));
    return d;
}
__device__ __forceinline__ void up2(unsigned long long v, float& x, float& y) {
    asm("mov.b64 {%0,%1},%2;" : "=f"(x), "=f"(y) : "l"(v));
}
__device__ __forceinline__ unsigned fkey(float f) {
    unsigned u = __float_as_uint(f);
    return (u & 0x80000000u) ? ~u : (u | 0x80000000u);
}

#define NTH 512
#define NWARP (NTH / 32)

__host__ __device__ constexpr size_t smem_words(int IC, int NF, int KS, int SIN) {
    const int T = 8, PAD = KS - 1, SOUT = SIN + KS - 1;
    const int SMROW = SIN + 2 * PAD + T, NPAIR = NF / 2;
    return (size_t)2 * IC * SMROW   // dup input
         + (size_t)2 * NPAIR * IC * KS + 2 * NPAIR
         + (size_t)NF * SOUT
         + (size_t)NWARP * 256 + 64;
}

// fused layer: grouped conv(+fold) + k-max + tanh. grid = (NG, B).
template <int IC, int NF, int KS, int SIN, int KOUT, bool GATHER>
__global__ void __launch_bounds__(NTH, 1)
layer_kernel(const float* __restrict__ xin, const int* __restrict__ tokens,
             const float* __restrict__ emb, const float* __restrict__ w,
             const float* __restrict__ bias, float* __restrict__ yout) {
    constexpr int T = 8, PAD = KS - 1, SOUT = SIN + KS - 1;
    constexpr int SMROW = SIN + 2 * PAD + T;
    constexpr int NPAIR = NF / 2;
    constexpr int NT = (SOUT + T - 1) / T;
    constexpr int IPG = IC / 2;  // orig in-channels per group

    extern __shared__ float sm[];
    float* sm_in = sm;                              // 2*IC*SMROW, dup pairs (v,v)
    float* sm_w  = sm_in + 2 * IC * SMROW;          // NPAIR*IC*KS packed f32x2
    float* sm_b2 = sm_w + 2 * NPAIR * IC * KS;      // NPAIR packed f32x2
    float* sm_out = sm_b2 + 2 * NPAIR;              // NF * SOUT pre-pool
    unsigned* sm_hist = (unsigned*)(sm_out + NF * SOUT);  // NWARP * 256

    const int j = blockIdx.x, b = blockIdx.y, tid = threadIdx.x;
    const int NG = gridDim.x;

    for (int i = tid; i < 2 * IC * SMROW; i += NTH) sm_in[i] = 0.f;
    __syncthreads();

    if constexpr (GATHER) {
        for (int i = tid; i < SIN; i += NTH) {
            int tok = tokens[b * SIN + i];
            float2 e = ((const float2*)emb)[tok * 32 + j];  // emb ch 2j,2j+1
            ((float2*)sm_in)[PAD + i]         = make_float2(e.x, e.x);
            ((float2*)sm_in)[SMROW + PAD + i] = make_float2(e.y, e.y);
        }
    } else {
        const float4* src =
            (const float4*)(xin + ((size_t)b * (NG * IC) + (size_t)j * IC) * SIN);
        for (int i = tid; i < IC * SIN / 4; i += NTH) {
            int ic = i / (SIN / 4), s4 = i - ic * (SIN / 4);
            float4 v = src[i];
            float2* d = (float2*)sm_in + ic * SMROW + PAD + s4 * 4;
            d[0] = make_float2(v.x, v.x);
            d[1] = make_float2(v.y, v.y);
            d[2] = make_float2(v.z, v.z);
            d[3] = make_float2(v.w, v.w);
        }
    }
    for (int i = tid; i < NPAIR * IC * KS; i += NTH) {
        int fp = i % NPAIR, rest = i / NPAIR;
        int k = rest % KS, ic = rest / KS;
        int g = 2 * j + (ic >= IPG ? 1 : 0);
        int ich = ic % IPG;
        const float* wb = w + (size_t)(g * NF) * IPG * KS + ich * KS + k;
        sm_w[2 * i]     = wb[(size_t)(2 * fp) * (IPG * KS)];
        sm_w[2 * i + 1] = wb[(size_t)(2 * fp + 1) * (IPG * KS)];
    }
    for (int i = tid; i < NPAIR; i += NTH) {
        sm_b2[2 * i]     = bias[2 * j * NF + 2 * i]     + bias[(2 * j + 1) * NF + 2 * i];
        sm_b2[2 * i + 1] = bias[2 * j * NF + 2 * i + 1] + bias[(2 * j + 1) * NF + 2 * i + 1];
    }
    __syncthreads();

    // conv: each thread = one output-channel pair (f32x2) x T seq positions
    for (int t = tid; t < NPAIR * NT; t += NTH) {
        const int fp = t % NPAIR, ot = t / NPAIR, o0 = ot * T;
        unsigned long long acc[T];
        unsigned long long b2 = *(const unsigned long long*)(sm_b2 + 2 * fp);
#pragma unroll
        for (int tt = 0; tt < T; tt++) acc[tt] = b2;
        const unsigned long long* xrow = (const unsigned long long*)sm_in + o0;
        const unsigned long long* wrow = (const unsigned long long*)sm_w + fp;
        for (int ic = 0; ic < IC; ic++) {
            unsigned long long wd[T + KS - 1];
#pragma unroll
            for (int q = 0; q < T + KS - 1; q++) wd[q] = xrow[ic * SMROW + q];
#pragma unroll
            for (int k = 0; k < KS; k++) {
                unsigned long long wk = wrow[(ic * KS + k) * NPAIR];
#pragma unroll
                for (int tt = 0; tt < T; tt++) acc[tt] = fma2(wd[k + tt], wk, acc[tt]);
            }
        }
#pragma unroll
        for (int tt = 0; tt < T; tt++) {
            if (o0 + tt < SOUT) {
                float x_, y_;
                up2(acc[tt], x_, y_);
                sm_out[(2 * fp) * SOUT + o0 + tt]     = x_;
                sm_out[(2 * fp + 1) * SOUT + o0 + tt] = y_;
            }
        }
    }
    __syncthreads();

    // per-channel warp radix-select top-KOUT (order preserving) + tanh + store
    const int warp = tid >> 5, lane = tid & 31;
    unsigned* hist = sm_hist + warp * 256;
    const unsigned lmlt = (1u << lane) - 1u;
    for (int c = warp; c < NF; c += NWARP) {
        const float* vals = sm_out + c * SOUT;
        unsigned prefix = 0, r = KOUT;
#pragma unroll
        for (int pass = 0; pass < 4; pass++) {
            const int shift = 24 - 8 * pass;
#pragma unroll
            for (int m = 0; m < 8; m++) hist[lane * 8 + m] = 0;
            __syncwarp();
            for (int i = lane; i < SOUT; i += 32) {
                unsigned ky = fkey(vals[i]);
                bool ok = true;
                if (pass > 0) ok = ((ky ^ prefix) >> (shift + 8)) == 0;
                if (ok) atomicAdd(&hist[(ky >> shift) & 255], 1u);
            }
            __syncwarp();
            unsigned h[8], s = 0;
#pragma unroll
            for (int m = 0; m < 8; m++) { h[m] = hist[lane * 8 + m]; s += h[m]; }
            unsigned run = s;  // suffix-sum over lanes (bins ascend with lane)
#pragma unroll
            for (int d = 1; d < 32; d <<= 1) {
                unsigned v = __shfl_down_sync(FULLMASK, run, d);
                if (lane + d < 32) run += v;
            }
            unsigned above = run - s;
            bool mine = (above < r) && (run >= r);
            unsigned a2 = above, gtc = 0;
            int bsel = 0;
            bool found = false;
#pragma unroll
            for (int m = 7; m >= 0; m--) {
                unsigned na = a2 + h[m];
                if (!found && na >= r) { found = true; bsel = lane * 8 + m; gtc = a2; }
                a2 = na;
            }
            unsigned msk = __ballot_sync(FULLMASK, mine);
            int src = __ffs(msk) - 1;
            bsel = __shfl_sync(FULLMASK, bsel, src);
            gtc  = __shfl_sync(FULLMASK, gtc, src);
            prefix |= ((unsigned)bsel) << shift;
            r -= gtc;  // remaining ==threshold elements to keep (leftmost)
        }
        float* dst = yout + ((size_t)b * (NG * NF) + (size_t)j * NF + c) * KOUT;
        const unsigned thr = prefix;
        int kept = 0, eqbudget = (int)r;
        for (int base = 0; base < SOUT; base += 32) {
            int i = base + lane;
            bool valid = i < SOUT;
            float v = valid ? vals[i] : 0.f;
            unsigned ky = fkey(v);
            bool gt = valid && (ky > thr);
            bool eq = valid && (ky == thr);
            unsigned eqm = __ballot_sync(FULLMASK, eq);
            int eqbefore = __popc(eqm & lmlt);
            bool keep = gt || (eq && (eqbefore < eqbudget));
            unsigned km = __ballot_sync(FULLMASK, keep);
            if (keep) dst[kept + __popc(km & lmlt)] = tanhf(v);
            kept += __popc(km);
            eqbudget -= __popc(km & eqm);
        }
    }
}

__global__ void fc_kernel(const float* __restrict__ x, const float* __restrict__ fcw,
                          const float* __restrict__ fcb, float* __restrict__ out) {
    int b = blockIdx.x, m = threadIdx.x >> 5, lane = threadIdx.x & 31;
    const float* xr = x + b * 352;
    const float* wr = fcw + m * 352;
    float s = 0.f;
    for (int i = lane; i < 352; i += 32) s += xr[i] * wr[i];
#pragma unroll
    for (int d = 16; d > 0; d >>= 1) s += __shfl_down_sync(FULLMASK, s, d);
    if (lane == 0) out[b * 6 + m] = s + fcb[m];
}

extern "C" void kernel_launch(void* const* d_in, const int* in_sizes, int n_in,
                              void* d_out, int out_size) {
    const int*   tokens = (const int*)d_in[0];
    const float* emb = (const float*)d_in[1];
    const float* w1 = (const float*)d_in[2];
    const float* b1 = (const float*)d_in[3];
    const float* w2 = (const float*)d_in[4];
    const float* b2 = (const float*)d_in[5];
    const float* w3 = (const float*)d_in[6];
    const float* b3 = (const float*)d_in[7];
    const float* w4 = (const float*)d_in[8];
    const float* b4 = (const float*)d_in[9];
    const float* fcw = (const float*)d_in[10];
    const float* fcb = (const float*)d_in[11];
    float* out = (float*)d_out;

    float *y1, *y2, *y3, *y4;
    cudaGetSymbolAddress((void**)&y1, g_y1);
    cudaGetSymbolAddress((void**)&y2, g_y2);
    cudaGetSymbolAddress((void**)&y3, g_y3);
    cudaGetSymbolAddress((void**)&y4, g_y4);

    auto k1 = layer_kernel<2, 10, 7, 1024, 768, true>;
    auto k2 = layer_kernel<20, 14, 5, 768, 512, false>;
    auto k3 = layer_kernel<28, 18, 5, 512, 256, false>;
    auto k4 = layer_kernel<36, 22, 3, 256, 4, false>;
    size_t s1 = smem_words(2, 10, 7, 1024) * 4;
    size_t s2 = smem_words(20, 14, 5, 768) * 4;
    size_t s3 = smem_words(28, 18, 5, 512) * 4;
    size_t s4 = smem_words(36, 22, 3, 256) * 4;
    cudaFuncSetAttribute(k1, cudaFuncAttributeMaxDynamicSharedMemorySize, (int)s1);
    cudaFuncSetAttribute(k2, cudaFuncAttributeMaxDynamicSharedMemorySize, (int)s2);
    cudaFuncSetAttribute(k3, cudaFuncAttributeMaxDynamicSharedMemorySize, (int)s3);
    cudaFuncSetAttribute(k4, cudaFuncAttributeMaxDynamicSharedMemorySize, (int)s4);

    k1<<<dim3(32, 64), NTH, s1>>>(nullptr, tokens, emb, w1, b1, y1);
    k2<<<dim3(16, 64), NTH, s2>>>(y1, nullptr, nullptr, w2, b2, y2);
    k3<<<dim3(8, 64),  NTH, s3>>>(y2, nullptr, nullptr, w3, b3, y3);
    k4<<<dim3(4, 64),  NTH, s4>>>(y3, nullptr, nullptr, w4, b4, y4);
    fc_kernel<<<64, 192>>>(y4, fcw, fcb, out);
}

// round 6
// speedup vs baseline: 1.1401x; 1.1401x over previous
#include <cuda_runtime.h>
#include <math.h>
#include <stdint.h>

#define FULLMASK 0xffffffffu

// pooled outputs (inputs to next layer)
__device__ __align__(16) float g_y1[64 * 320 * 768];
__device__ __align__(16) float g_y2[64 * 224 * 512];
__device__ __align__(16) float g_y3[64 * 144 * 256];
__device__ __align__(16) float g_y4[64 * 88 * 4];
// pre-pool conv outputs
__device__ __align__(16) float g_p1[64 * 320 * 1030];
__device__ __align__(16) float g_p2[64 * 224 * 772];
__device__ __align__(16) float g_p3[64 * 144 * 516];
__device__ __align__(16) float g_p4[64 * 88 * 258];

__device__ __forceinline__ unsigned long long fma2(unsigned long long a,
                                                   unsigned long long b,
                                                   unsigned long long c) {
    unsigned long long d;
    asm("fma.rn.f32x2 %0,%1,%2,%3;" : "=l"(d) : "l"(a), "l"(b), "l"(c));
    return d;
}
__device__ __forceinline__ void up2(unsigned long long v, float& x, float& y) {
    asm("mov.b64 {%0,%1},%2;" : "=f"(x), "=f"(y) : "l"(v));
}
__device__ __forceinline__ unsigned fkey(float f) {
    unsigned u = __float_as_uint(f);
    return (u & 0x80000000u) ? ~u : (u | 0x80000000u);
}

#define CTH 128   // conv block
#define TS  128   // seq outputs per conv CTA
#define TT  8     // outputs per thread

__host__ __device__ constexpr int conv_smem_words(int IC, int NF, int KS) {
    const int SMT = TS + 2 * KS;
    return 2 * IC * SMT + 2 * (NF / 2) * IC * KS + 2 * (NF / 2);
}

// grouped conv (+fold) -> pre-pool gmem. grid.x = NG*NTILE, grid.y = B.
template <int IC, int NF, int KS, int SIN, bool GATHER>
__global__ void __launch_bounds__(CTH)
conv_kernel(const float* __restrict__ xin, const int* __restrict__ tokens,
            const float* __restrict__ emb, const float* __restrict__ w,
            const float* __restrict__ bias, float* __restrict__ pre) {
    constexpr int PAD = KS - 1, SOUT = SIN + KS - 1;
    constexpr int SMT = TS + 2 * KS;
    constexpr int NPAIR = NF / 2;
    constexpr int NTILE = (SOUT + TS - 1) / TS;
    constexpr int IPG = IC / 2;

    extern __shared__ float sm[];
    float* sm_in = sm;                          // IC*SMT dup pairs (v,v)
    float* sm_w  = sm_in + 2 * IC * SMT;        // NPAIR*IC*KS f32x2
    float* sm_b2 = sm_w + 2 * NPAIR * IC * KS;  // NPAIR f32x2

    const int j = blockIdx.x / NTILE;
    const int st = blockIdx.x % NTILE;
    const int b = blockIdx.y, tid = threadIdx.x;
    const int NG = gridDim.x / NTILE;
    const int CHT = NG * NF;
    const int obase = st * TS;

    // stage input tile (xpad[obase + p], p in [0, SMT))
    if constexpr (GATHER) {
        for (int p = tid; p < SMT; p += CTH) {
            int i = obase + p - PAD;
            float2 e = make_float2(0.f, 0.f);
            if (i >= 0 && i < SIN) {
                int tok = tokens[b * SIN + i];
                e = ((const float2*)emb)[tok * 32 + j];
            }
            ((float2*)sm_in)[p]       = make_float2(e.x, e.x);
            ((float2*)sm_in)[SMT + p] = make_float2(e.y, e.y);
        }
    } else {
        const float* src = xin + ((size_t)b * (NG * IC) + (size_t)j * IC) * SIN;
        for (int idx = tid; idx < IC * SMT; idx += CTH) {
            int ic = idx / SMT, p = idx % SMT;
            int i = obase + p - PAD;
            float v = (i >= 0 && i < SIN) ? src[(size_t)ic * SIN + i] : 0.f;
            ((float2*)sm_in)[idx] = make_float2(v, v);
        }
    }
    for (int i = tid; i < NPAIR * IC * KS; i += CTH) {
        int fp = i % NPAIR, rest = i / NPAIR;
        int k = rest % KS, ic = rest / KS;
        int g = 2 * j + (ic >= IPG ? 1 : 0);
        int ich = ic % IPG;
        const float* wb = w + (size_t)(g * NF) * IPG * KS + ich * KS + k;
        sm_w[2 * i]     = wb[(size_t)(2 * fp) * (IPG * KS)];
        sm_w[2 * i + 1] = wb[(size_t)(2 * fp + 1) * (IPG * KS)];
    }
    for (int i = tid; i < NPAIR; i += CTH) {
        sm_b2[2 * i]     = bias[2 * j * NF + 2 * i]     + bias[(2 * j + 1) * NF + 2 * i];
        sm_b2[2 * i + 1] = bias[2 * j * NF + 2 * i + 1] + bias[(2 * j + 1) * NF + 2 * i + 1];
    }
    __syncthreads();

    constexpr int ITEMS = NPAIR * (TS / TT);
    for (int t = tid; t < ITEMS; t += CTH) {
        const int fp = t % NPAIR, ot = t / NPAIR, o0 = ot * TT;
        unsigned long long acc[TT];
        unsigned long long b2 = *(const unsigned long long*)(sm_b2 + 2 * fp);
#pragma unroll
        for (int tt = 0; tt < TT; tt++) acc[tt] = b2;
        const unsigned long long* xrow = (const unsigned long long*)sm_in + o0;
        const unsigned long long* wrow = (const unsigned long long*)sm_w + fp;
        for (int ic = 0; ic < IC; ic++) {
            unsigned long long wd[TT + KS - 1];
#pragma unroll
            for (int q = 0; q < TT + KS - 1; q++) wd[q] = xrow[ic * SMT + q];
#pragma unroll
            for (int k = 0; k < KS; k++) {
                unsigned long long wk = wrow[(ic * KS + k) * NPAIR];
#pragma unroll
                for (int tt = 0; tt < TT; tt++) acc[tt] = fma2(wd[k + tt], wk, acc[tt]);
            }
        }
        const int c0 = j * NF + 2 * fp;
        float* d0 = pre + ((size_t)b * CHT + c0) * SOUT;
        float* d1 = d0 + SOUT;
#pragma unroll
        for (int tt = 0; tt < TT; tt++) {
            int o = obase + o0 + tt;
            if (o < SOUT) {
                float x_, y_;
                up2(acc[tt], x_, y_);
                d0[o] = x_;
                d1[o] = y_;
            }
        }
    }
}

// warp-per-row radix-select top-KOUT (order preserving) + tanh.
// grid.x = B*CH/4, block 128 (4 warps).
template <int SOUT, int KOUT>
__global__ void __launch_bounds__(128)
kmax_kernel(const float* __restrict__ pre, float* __restrict__ yout) {
    __shared__ unsigned hists[4][256];
    const int warp = threadIdx.x >> 5, lane = threadIdx.x & 31;
    const unsigned lmlt = (1u << lane) - 1u;
    unsigned* hist = hists[warp];

    const int row = blockIdx.x * 4 + warp;
    const float* vals = pre + (size_t)row * SOUT;
    float* dst = yout + (size_t)row * KOUT;

    unsigned prefix = 0, r = KOUT;
#pragma unroll
    for (int pass = 0; pass < 4; pass++) {
        const int shift = 24 - 8 * pass;
#pragma unroll
        for (int m = 0; m < 8; m++) hist[lane * 8 + m] = 0;
        __syncwarp();
        for (int i = lane; i < SOUT; i += 32) {
            unsigned ky = fkey(__ldg(vals + i));
            bool ok = true;
            if (pass > 0) ok = ((ky ^ prefix) >> (shift + 8)) == 0;
            if (ok) atomicAdd(&hist[(ky >> shift) & 255], 1u);
        }
        __syncwarp();
        unsigned h[8], s = 0;
#pragma unroll
        for (int m = 0; m < 8; m++) { h[m] = hist[lane * 8 + m]; s += h[m]; }
        unsigned run = s;  // suffix sum over lanes (bins ascend with lane)
#pragma unroll
        for (int d = 1; d < 32; d <<= 1) {
            unsigned v = __shfl_down_sync(FULLMASK, run, d);
            if (lane + d < 32) run += v;
        }
        unsigned above = run - s;
        bool mine = (above < r) && (run >= r);
        unsigned a2 = above, gtc = 0;
        int bsel = 0;
        bool found = false;
#pragma unroll
        for (int m = 7; m >= 0; m--) {
            unsigned na = a2 + h[m];
            if (!found && na >= r) { found = true; bsel = lane * 8 + m; gtc = a2; }
            a2 = na;
        }
        unsigned msk = __ballot_sync(FULLMASK, mine);
        int src = __ffs(msk) - 1;
        bsel = __shfl_sync(FULLMASK, bsel, src);
        gtc  = __shfl_sync(FULLMASK, gtc, src);
        prefix |= ((unsigned)bsel) << shift;
        r -= gtc;  // remaining ==threshold elements to keep (leftmost)
    }
    const unsigned thr = prefix;
    int kept = 0, eqbudget = (int)r;
    for (int base = 0; base < SOUT; base += 32) {
        int i = base + lane;
        bool valid = i < SOUT;
        float v = valid ? __ldg(vals + i) : 0.f;
        unsigned ky = fkey(v);
        bool gt = valid && (ky > thr);
        bool eq = valid && (ky == thr);
        unsigned eqm = __ballot_sync(FULLMASK, eq);
        int eqbefore = __popc(eqm & lmlt);
        bool keep = gt || (eq && (eqbefore < eqbudget));
        unsigned km = __ballot_sync(FULLMASK, keep);
        if (keep) dst[kept + __popc(km & lmlt)] = tanhf(v);
        kept += __popc(km);
        eqbudget -= __popc(km & eqm);
    }
}

__global__ void fc_kernel(const float* __restrict__ x, const float* __restrict__ fcw,
                          const float* __restrict__ fcb, float* __restrict__ out) {
    int b = blockIdx.x, m = threadIdx.x >> 5, lane = threadIdx.x & 31;
    const float* xr = x + b * 352;
    const float* wr = fcw + m * 352;
    float s = 0.f;
    for (int i = lane; i < 352; i += 32) s += xr[i] * wr[i];
#pragma unroll
    for (int d = 16; d > 0; d >>= 1) s += __shfl_down_sync(FULLMASK, s, d);
    if (lane == 0) out[b * 6 + m] = s + fcb[m];
}

extern "C" void kernel_launch(void* const* d_in, const int* in_sizes, int n_in,
                              void* d_out, int out_size) {
    const int*   tokens = (const int*)d_in[0];
    const float* emb = (const float*)d_in[1];
    const float* w1 = (const float*)d_in[2];
    const float* b1 = (const float*)d_in[3];
    const float* w2 = (const float*)d_in[4];
    const float* b2 = (const float*)d_in[5];
    const float* w3 = (const float*)d_in[6];
    const float* b3 = (const float*)d_in[7];
    const float* w4 = (const float*)d_in[8];
    const float* b4 = (const float*)d_in[9];
    const float* fcw = (const float*)d_in[10];
    const float* fcb = (const float*)d_in[11];
    float* out = (float*)d_out;

    float *y1, *y2, *y3, *y4, *p1, *p2, *p3, *p4;
    cudaGetSymbolAddress((void**)&y1, g_y1);
    cudaGetSymbolAddress((void**)&y2, g_y2);
    cudaGetSymbolAddress((void**)&y3, g_y3);
    cudaGetSymbolAddress((void**)&y4, g_y4);
    cudaGetSymbolAddress((void**)&p1, g_p1);
    cudaGetSymbolAddress((void**)&p2, g_p2);
    cudaGetSymbolAddress((void**)&p3, g_p3);
    cudaGetSymbolAddress((void**)&p4, g_p4);

    auto c1 = conv_kernel<2, 10, 7, 1024, true>;
    auto c2 = conv_kernel<20, 14, 5, 768, false>;
    auto c3 = conv_kernel<28, 18, 5, 512, false>;
    auto c4 = conv_kernel<36, 22, 3, 256, false>;
    size_t s1 = conv_smem_words(2, 10, 7) * 4;
    size_t s2 = conv_smem_words(20, 14, 5) * 4;
    size_t s3 = conv_smem_words(28, 18, 5) * 4;
    size_t s4 = conv_smem_words(36, 22, 3) * 4;
    cudaFuncSetAttribute(c1, cudaFuncAttributeMaxDynamicSharedMemorySize, (int)s1);
    cudaFuncSetAttribute(c2, cudaFuncAttributeMaxDynamicSharedMemorySize, (int)s2);
    cudaFuncSetAttribute(c3, cudaFuncAttributeMaxDynamicSharedMemorySize, (int)s3);
    cudaFuncSetAttribute(c4, cudaFuncAttributeMaxDynamicSharedMemorySize, (int)s4);

    // NTILE = ceil(SOUT / 128): L1 1030->9, L2 772->7, L3 516->5, L4 258->3
    c1<<<dim3(32 * 9, 64), CTH, s1>>>(nullptr, tokens, emb, w1, b1, p1);
    kmax_kernel<1030, 768><<<64 * 320 / 4, 128>>>(p1, y1);
    c2<<<dim3(16 * 7, 64), CTH, s2>>>(y1, nullptr, nullptr, w2, b2, p2);
    kmax_kernel<772, 512><<<64 * 224 / 4, 128>>>(p2, y2);
    c3<<<dim3(8 * 5, 64), CTH, s3>>>(y2, nullptr, nullptr, w3, b3, p3);
    kmax_kernel<516, 256><<<64 * 144 / 4, 128>>>(p3, y3);
    c4<<<dim3(4 * 3, 64), CTH, s4>>>(y3, nullptr, nullptr, w4, b4, p4);
    kmax_kernel<258, 4><<<64 * 88 / 4, 128>>>(p4, y4);
    fc_kernel<<<64, 192>>>(y4, fcw, fcb, out);
}